// round 12
// baseline (speedup 1.0000x reference)
#include <cuda_runtime.h>
#include <cstdint>

#define NTOK 65536
#define DDIM 2048
#define KEXP 64
#define BM   128
#define KC   32
#define NCHUNK (DDIM / KC)          // 64
#define AROW_B 80                   // bytes per A row (32 f16 data = 64B + 16 pad) -> ldmatrix conflict-free
#define A_STAGE_BYTES (BM * AROW_B) // 10240
#define SM_B_OFF (2 * A_STAGE_BYTES)         // 20480
#define B_STAGE_BYTES 4096                   // [ks(2)][nb(8)][64 words] f16-packed
#define SMEM_TOTAL 34816                     // >= 2A+2B (28672) and >= ls 128*68*4
#define LS_STRIDE 68
#define TIE_TAU 2e-3f
#define MAXFIX 8192

// W pre-converted to fp16, FRAGMENT-MAJOR for m16n8k16 B operand:
// word index = (kb*8 + nb)*64 + lane*2 + reg
//   halves (lo,hi of word) = W[n][k0], W[n][k0+1]
//   n = nb*8 + (lane>>2), k0 = kb*16 + (lane&3)*2 + reg*8
__device__ uint32_t g_Wf[128 * 8 * 64];
__device__ int g_cnt;
__device__ int g_rows[MAXFIX];

#define CVT_F16X2(res, f_lo, f_hi) \
    asm("cvt.rn.f16x2.f32 %0, %1, %2;" : "=r"(res) : "f"(f_hi), "f"(f_lo))

__global__ void wprep_kernel(const float* __restrict__ W) {
    int i = blockIdx.x * 256 + threadIdx.x;          // 0 .. 65535
    if (i == 0) g_cnt = 0;                           // reset flag list every launch
    int reg  = i & 1;
    int lane = (i >> 1) & 31;
    int nb   = (i >> 6) & 7;
    int kb   = i >> 9;
    int n  = nb * 8 + (lane >> 2);
    int k0 = kb * 16 + (lane & 3) * 2 + reg * 8;
    float v0 = W[n * DDIM + k0];
    float v1 = W[n * DDIM + k0 + 1];
    uint32_t w;
    CVT_F16X2(w, v0, v1);
    g_Wf[i] = w;
}

#define CP16(dst_u32, src_ptr) \
    asm volatile("cp.async.cg.shared.global [%0], [%1], 16;" :: "r"(dst_u32), "l"(src_ptr))
#define CP_COMMIT() asm volatile("cp.async.commit_group;" ::: "memory")
#define STS128(addr, r0, r1, r2, r3) \
    asm volatile("st.shared.v4.b32 [%0], {%1, %2, %3, %4};" \
                 :: "r"((uint32_t)(addr)), "r"(r0), "r"(r1), "r"(r2), "r"(r3) : "memory")
#define LDMATRIX_X4(r0, r1, r2, r3, addr) \
    asm volatile("ldmatrix.sync.aligned.m8n8.x4.shared.b16 {%0,%1,%2,%3}, [%4];" \
                 : "=r"(r0), "=r"(r1), "=r"(r2), "=r"(r3) : "r"((uint32_t)(addr)))

#define MMA_F16(c, a, b0_, b1_) \
    asm volatile("mma.sync.aligned.m16n8k16.row.col.f32.f16.f16.f32 " \
                 "{%0,%1,%2,%3}, {%4,%5,%6,%7}, {%8,%9}, {%0,%1,%2,%3};" \
                 : "+f"((c)[0]), "+f"((c)[1]), "+f"((c)[2]), "+f"((c)[3]) \
                 : "r"((a)[0]), "r"((a)[1]), "r"((a)[2]), "r"((a)[3]), \
                   "r"(b0_), "r"(b1_))

__global__ __launch_bounds__(256, 3)
void top2gate_tc(const float* __restrict__ x,
                 const float* __restrict__ b,
                 float* __restrict__ out) {
    extern __shared__ char smem[];
    uint32_t sb;
    asm("{ .reg .u64 t; cvta.to.shared.u64 t, %1; cvt.u32.u64 %0, t; }"
        : "=r"(sb) : "l"((const void*)smem));

    __shared__ float s_bias[KEXP];
    __shared__ int   s_i1[BM], s_i2[BM];
    __shared__ float s_q1[BM], s_q2[BM];

    const int tid  = threadIdx.x;
    const int lane = tid & 31;
    const int wid  = tid >> 5;
    const int g    = lane >> 2;       // groupID 0..7
    const int tg   = lane & 3;        // tid-in-group
    const int mg   = wid >> 1;        // m-group 0..3  (M32 tile)
    const int ng   = wid & 1;         // n-group 0..1  (N32 tile)
    const int m_base = mg * 32;
    const int row0 = blockIdx.x * BM;

    if (tid < KEXP) s_bias[tid] = b[tid];

    float acc[2][4][4];
    #pragma unroll
    for (int ti = 0; ti < 2; ti++)
        #pragma unroll
        for (int j = 0; j < 4; j++)
            #pragma unroll
            for (int c = 0; c < 4; c++) acc[ti][j][c] = 0.f;

    // producer mapping: thread -> (row pr, k-half kh2); 16 fp32 -> 8 f16x2 -> 2 STS.128
    const int pr  = tid >> 1;         // 0..127
    const int kh2 = tid & 1;          // 0..1 (16 floats each)
    const float* xrow = x + (size_t)(row0 + pr) * DDIM + kh2 * 16;
    const uint32_t sts_base = sb + (uint32_t)(pr * AROW_B + kh2 * 32);

    // ldmatrix lane->tile mapping: tiles (m0-7,klo)(m8-15,klo)(m0-7,khi)(m8-15,khi)
    const int lm_kh = (lane >> 4) & 1;
    const int lm_m  = ((lane >> 3) & 1) * 8 + (lane & 7);
    const uint32_t lm_base = sb + (uint32_t)((m_base + lm_m) * AROW_B + lm_kh * 16);

    auto ldgA = [&](int t, float4* v) {
        const float* p = xrow + t * KC;
        v[0] = *(const float4*)(p + 0);
        v[1] = *(const float4*)(p + 4);
        v[2] = *(const float4*)(p + 8);
        v[3] = *(const float4*)(p + 12);
    };
    auto prodA_sts = [&](int t, const float4* v) {
        uint32_t h[8];
        CVT_F16X2(h[0], v[0].x, v[0].y);  CVT_F16X2(h[1], v[0].z, v[0].w);
        CVT_F16X2(h[2], v[1].x, v[1].y);  CVT_F16X2(h[3], v[1].z, v[1].w);
        CVT_F16X2(h[4], v[2].x, v[2].y);  CVT_F16X2(h[5], v[2].z, v[2].w);
        CVT_F16X2(h[6], v[3].x, v[3].y);  CVT_F16X2(h[7], v[3].z, v[3].w);
        uint32_t ad = sts_base + (uint32_t)((t & 1) * A_STAGE_BYTES);
        STS128(ad,      h[0], h[1], h[2], h[3]);
        STS128(ad + 16, h[4], h[5], h[6], h[7]);
    };
    auto issueB = [&](int t) {
        uint32_t db = sb + SM_B_OFF + (uint32_t)((t & 1) * B_STAGE_BYTES);
        CP16(db + (uint32_t)tid * 16, (const void*)(g_Wf + t * 1024 + tid * 4));
        CP_COMMIT();
    };

    // prologue: A(0) in smem, B(0) in flight, A(1) in registers
    float4 vp[4];
    {
        float4 v0[4];
        ldgA(0, v0);
        prodA_sts(0, v0);
        issueB(0);
        ldgA(1, vp);
    }

    for (int t = 0; t < NCHUNK; t++) {
        // own B(<=t) copies done, then barrier -> ALL threads' copies + STS visible
        asm volatile("cp.async.wait_group 0;" ::: "memory");
        __syncthreads();
        // stage (t+1)&1 is now safe to overwrite (its readers ran in iter t-1)
        if (t + 1 < NCHUNK) {
            prodA_sts(t + 1, vp);
            issueB(t + 1);
        }
        if (t + 2 < NCHUNK) ldgA(t + 2, vp);   // lands during the MMA block

        const uint32_t lmA = lm_base + (uint32_t)((t & 1) * A_STAGE_BYTES);
        const uint32_t dbB = sb + SM_B_OFF + (uint32_t)((t & 1) * B_STAGE_BYTES);

        #pragma unroll
        for (int ks = 0; ks < 2; ks++) {
            uint32_t aF0[4], aF1[4];
            LDMATRIX_X4(aF0[0], aF0[1], aF0[2], aF0[3], lmA + ks * 32);
            LDMATRIX_X4(aF1[0], aF1[1], aF1[2], aF1[3], lmA + ks * 32 + 16 * AROW_B);
            #pragma unroll
            for (int j = 0; j < 4; j++) {
                uint32_t b0, b1;
                uint32_t ad = dbB + (uint32_t)((ks * 512 + (ng * 4 + j) * 64 + lane * 2) * 4);
                asm volatile("ld.shared.v2.b32 {%0,%1}, [%2];"
                             : "=r"(b0), "=r"(b1) : "r"(ad));
                MMA_F16(acc[0][j], aF0, b0, b1);
                MMA_F16(acc[1][j], aF1, b0, b1);
            }
        }
    }
    __syncthreads();   // all MMA reads done before ls overlay

    // ---- epilogue: park logits in smem (overlays stages) ----
    float* ls = (float*)smem;   // [BM][LS_STRIDE]
    #pragma unroll
    for (int ti = 0; ti < 2; ti++)
        #pragma unroll
        for (int j = 0; j < 4; j++) {
            int r = m_base + ti * 16 + g;
            int c = (ng * 4 + j) * 8 + tg * 2;
            *(float2*)&ls[r * LS_STRIDE + c]       = make_float2(acc[ti][j][0], acc[ti][j][1]);
            *(float2*)&ls[(r + 8) * LS_STRIDE + c] = make_float2(acc[ti][j][2], acc[ti][j][3]);
        }
    __syncthreads();

    float* out_p = out;
    float* out_e = out + (size_t)NTOK * KEXP;
    float* out_l = out_e + NTOK;

    if (tid < BM) {
        const int row = tid;
        const float* lrow = &ls[row * LS_STRIDE];
        float m1 = -1e30f, m2 = -1e30f, m3 = -1e30f;
        int i1 = 0, i2 = 0;
        #pragma unroll
        for (int c = 0; c < KEXP; c++) {
            float v = lrow[c] + s_bias[c];
            if (v > m1)      { m3 = m2; m2 = m1; i2 = i1; m1 = v; i1 = c; }
            else if (v > m2) { m3 = m2; m2 = v;  i2 = c; }
            else if (v > m3) { m3 = v; }
        }
        // near-tie at top-2/top-3 boundary -> exact fp32 repair
        if (m2 - m3 < TIE_TAU) {
            int slot = atomicAdd(&g_cnt, 1);
            if (slot < MAXFIX) g_rows[slot] = row0 + row;
        }
        float Z = 0.f;
        #pragma unroll
        for (int c = 0; c < KEXP; c++) Z += expf(lrow[c] + s_bias[c] - m1);
        float p1 = 1.0f / Z;
        float p2 = expf(m2 - m1) / Z;
        float denom = p1 + p2 + 1e-9f;
        float q1 = p1 / denom, q2 = p2 / denom;
        float ent = -(q1 * logf(fmaxf(q1, 1e-12f)) + q2 * logf(fmaxf(q2, 1e-12f)));
        s_i1[row] = i1; s_i2[row] = i2; s_q1[row] = q1; s_q2[row] = q2;
        out_e[row0 + row] = ent;
    }
    __syncthreads();

    // coalesced sweep: top2_probs + logits (+bias)
    #pragma unroll
    for (int i = 0; i < 8; i++) {
        int idx = tid + 256 * i;        // 0..2047
        int row = idx >> 4;
        int col = (idx & 15) * 4;
        int i1 = s_i1[row], i2 = s_i2[row];
        float q1 = s_q1[row], q2 = s_q2[row];
        float4 pv;
        pv.x = (col + 0 == i1) ? q1 : ((col + 0 == i2) ? q2 : 0.f);
        pv.y = (col + 1 == i1) ? q1 : ((col + 1 == i2) ? q2 : 0.f);
        pv.z = (col + 2 == i1) ? q1 : ((col + 2 == i2) ? q2 : 0.f);
        pv.w = (col + 3 == i1) ? q1 : ((col + 3 == i2) ? q2 : 0.f);
        float4 lv;
        lv.x = ls[row * LS_STRIDE + col + 0] + s_bias[col + 0];
        lv.y = ls[row * LS_STRIDE + col + 1] + s_bias[col + 1];
        lv.z = ls[row * LS_STRIDE + col + 2] + s_bias[col + 2];
        lv.w = ls[row * LS_STRIDE + col + 3] + s_bias[col + 3];
        size_t gaddr = (size_t)(row0 + row) * KEXP + col;
        *(float4*)&out_p[gaddr] = pv;
        *(float4*)&out_l[gaddr] = lv;
    }
}

// exact-fp32 repair for near-tie rows
__global__ void __launch_bounds__(256, 4)
fix_kernel(const float* __restrict__ x, const float* __restrict__ W,
           const float* __restrict__ b, float* __restrict__ out) {
    __shared__ float sx[DDIM];
    __shared__ float sl[KEXP];
    const int tid = threadIdx.x;
    const int e   = tid >> 2;
    const int p   = tid & 3;
    const int n   = min(g_cnt, MAXFIX);

    float* out_p = out;
    float* out_e = out + (size_t)NTOK * KEXP;
    float* out_l = out_e + NTOK;

    for (int i = blockIdx.x; i < n; i += gridDim.x) {
        const int row = g_rows[i];
        for (int j = tid; j < DDIM; j += 256)
            sx[j] = x[(size_t)row * DDIM + j];
        __syncthreads();

        float s = 0.f;
        const float* wr = W + (size_t)e * DDIM + p;
        #pragma unroll 8
        for (int j = 0; j < DDIM / 4; j++)
            s = fmaf(sx[p + 4 * j], wr[4 * j], s);
        s += __shfl_xor_sync(0xFFFFFFFFu, s, 1);
        s += __shfl_xor_sync(0xFFFFFFFFu, s, 2);
        if (p == 0) sl[e] = s + b[e];
        __syncthreads();

        if (tid < KEXP) {
            float m1 = -1e30f, m2 = -1e30f;
            int i1 = 0, i2 = 0;
            #pragma unroll
            for (int c = 0; c < KEXP; c++) {
                float v = sl[c];
                if (v > m1)      { m2 = m1; i2 = i1; m1 = v; i1 = c; }
                else if (v > m2) { m2 = v;  i2 = c; }
            }
            float Z = 0.f;
            #pragma unroll
            for (int c = 0; c < KEXP; c++) Z += expf(sl[c] - m1);
            float p1 = 1.0f / Z;
            float p2 = expf(m2 - m1) / Z;
            float denom = p1 + p2 + 1e-9f;
            float q1 = p1 / denom, q2 = p2 / denom;
            size_t gr = (size_t)row * KEXP;
            out_l[gr + tid] = sl[tid];
            out_p[gr + tid] = (tid == i1) ? q1 : ((tid == i2) ? q2 : 0.f);
            if (tid == 0)
                out_e[row] = -(q1 * logf(fmaxf(q1, 1e-12f)) +
                               q2 * logf(fmaxf(q2, 1e-12f)));
        }
        __syncthreads();
    }
}

extern "C" void kernel_launch(void* const* d_in, const int* in_sizes, int n_in,
                              void* d_out, int out_size) {
    const float* x = (const float*)d_in[0];
    const float* W = (const float*)d_in[1];
    const float* b = (const float*)d_in[2];
    cudaFuncSetAttribute(top2gate_tc, cudaFuncAttributeMaxDynamicSharedMemorySize, SMEM_TOTAL);
    wprep_kernel<<<256, 256>>>(W);
    top2gate_tc<<<NTOK / BM, 256, SMEM_TOTAL>>>(x, b, (float*)d_out);
    fix_kernel<<<148, 256>>>(x, W, b, (float*)d_out);
}

// round 13
// speedup vs baseline: 1.1805x; 1.1805x over previous
#include <cuda_runtime.h>
#include <cstdint>

#define NTOK 65536
#define DDIM 2048
#define KEXP 64
#define BM   256
#define NTHR 512
#define KC   32
#define NCHUNK (DDIM / KC)          // 64
#define ASTRIDE 36                  // fp32 words per A row (32 data + 4 pad)
#define A_STAGE_BYTES (BM * ASTRIDE * 4)     // 36864
#define NSTAGE 2
#define SM_B_OFF (NSTAGE * A_STAGE_BYTES)    // 73728
#define B_STAGE_BYTES 4096                   // [ks(2)][nb(8)][64 words] f16-packed
#define SMEM_TOTAL (SM_B_OFF + NSTAGE * B_STAGE_BYTES)  // 81920 -> occ 2 @ 512 thr
#define LS_STRIDE 68
#define TIE_TAU 2e-3f
#define MAXFIX 8192

// W pre-converted to fp16, FRAGMENT-MAJOR for m16n8k16 B operand:
// word index = (kb*8 + nb)*64 + lane*2 + reg
//   halves (lo,hi of word) = W[n][k0], W[n][k0+1]
//   n = nb*8 + (lane>>2), k0 = kb*16 + (lane&3)*2 + reg*8
__device__ uint32_t g_Wf[128 * 8 * 64];
__device__ int g_cnt;
__device__ int g_rows[MAXFIX];

#define CVT_F16X2(res, f_lo, f_hi) \
    asm("cvt.rn.f16x2.f32 %0, %1, %2;" : "=r"(res) : "f"(f_hi), "f"(f_lo))

__global__ void wprep_kernel(const float* __restrict__ W) {
    int i = blockIdx.x * 256 + threadIdx.x;          // 0 .. 65535
    if (i == 0) g_cnt = 0;                           // reset flag list every launch
    int reg  = i & 1;
    int lane = (i >> 1) & 31;
    int nb   = (i >> 6) & 7;
    int kb   = i >> 9;
    int n  = nb * 8 + (lane >> 2);
    int k0 = kb * 16 + (lane & 3) * 2 + reg * 8;
    float v0 = W[n * DDIM + k0];
    float v1 = W[n * DDIM + k0 + 1];
    uint32_t w;
    CVT_F16X2(w, v0, v1);
    g_Wf[i] = w;
}

#define CP16(dst_u32, src_ptr) \
    asm volatile("cp.async.cg.shared.global [%0], [%1], 16;" :: "r"(dst_u32), "l"(src_ptr))
#define CP_COMMIT() asm volatile("cp.async.commit_group;" ::: "memory")

#define MMA_F16(c, a, b0_, b1_) \
    asm volatile("mma.sync.aligned.m16n8k16.row.col.f32.f16.f16.f32 " \
                 "{%0,%1,%2,%3}, {%4,%5,%6,%7}, {%8,%9}, {%0,%1,%2,%3};" \
                 : "+f"((c)[0]), "+f"((c)[1]), "+f"((c)[2]), "+f"((c)[3]) \
                 : "r"((a)[0]), "r"((a)[1]), "r"((a)[2]), "r"((a)[3]), \
                   "r"(b0_), "r"(b1_))

__global__ __launch_bounds__(NTHR, 2)
void top2gate_tc(const float* __restrict__ x,
                 const float* __restrict__ b,
                 float* __restrict__ out) {
    extern __shared__ char smem[];
    uint32_t sb;
    asm("{ .reg .u64 t; cvta.to.shared.u64 t, %1; cvt.u32.u64 %0, t; }"
        : "=r"(sb) : "l"((const void*)smem));

    __shared__ float s_bias[KEXP];
    __shared__ int   s_i1[BM], s_i2[BM];
    __shared__ float s_q1[BM], s_q2[BM];

    const int tid  = threadIdx.x;
    const int lane = tid & 31;
    const int wid  = tid >> 5;        // 0..15
    const int g    = lane >> 2;       // groupID 0..7
    const int tg   = lane & 3;        // tid-in-group
    const int r0w  = wid * 16;        // warp M-tile base (M16 x N64 per warp)
    const int row0 = blockIdx.x * BM;

    if (tid < KEXP) s_bias[tid] = b[tid];

    float acc[8][4];
    #pragma unroll
    for (int nb = 0; nb < 8; nb++)
        #pragma unroll
        for (int c = 0; c < 4; c++) acc[nb][c] = 0.f;

    // issue cp.async for chunk t into stage t & 1 (A raw fp32 rows + B fp16 frags)
    auto issue_chunk = [&](int t) {
        const int st = t & 1;
        const float* xs = x + (size_t)row0 * DDIM + t * KC;
        uint32_t da = sb + st * A_STAGE_BYTES;
        #pragma unroll
        for (int q = 0; q < 4; q++) {
            int idx = tid + NTHR * q;         // 0..2047
            int r   = idx >> 3;               // row 0..255
            int seg = idx & 7;                // 16B segment (32 floats/row)
            CP16(da + (uint32_t)(r * ASTRIDE + seg * 4) * 4,
                 xs + (size_t)r * DDIM + seg * 4);
        }
        if (tid < 256) {
            uint32_t db = sb + SM_B_OFF + st * B_STAGE_BYTES;
            CP16(db + (uint32_t)tid * 16, (const void*)(g_Wf + t * 1024 + tid * 4));
        }
        CP_COMMIT();
    };

    issue_chunk(0);

    for (int t = 0; t < NCHUNK; t++) {
        // stage (t+1)&1 is free: trailing sync of iteration t-1 drained readers
        if (t + 1 < NCHUNK) {
            issue_chunk(t + 1);
            asm volatile("cp.async.wait_group 1;" ::: "memory");   // group(t) done
        } else {
            asm volatile("cp.async.wait_group 0;" ::: "memory");
        }
        __syncthreads();

        const int st = t & 1;
        const float* A = (const float*)(smem + st * A_STAGE_BYTES);
        const uint32_t dbB = sb + SM_B_OFF + st * B_STAGE_BYTES;

        #pragma unroll
        for (int ks = 0; ks < 2; ks++) {
            // A fragments (M16): fp32 pairs -> packed f16x2
            uint32_t aF[4];
            {
                const int r = r0w + g;
                const int c0 = ks * 16 + tg * 2;
                float2 p0 = *(const float2*)&A[r * ASTRIDE + c0];
                float2 p1 = *(const float2*)&A[(r + 8) * ASTRIDE + c0];
                float2 p2 = *(const float2*)&A[r * ASTRIDE + c0 + 8];
                float2 p3 = *(const float2*)&A[(r + 8) * ASTRIDE + c0 + 8];
                CVT_F16X2(aF[0], p0.x, p0.y);
                CVT_F16X2(aF[1], p1.x, p1.y);
                CVT_F16X2(aF[2], p2.x, p2.y);
                CVT_F16X2(aF[3], p3.x, p3.y);
            }
            // 8 MMAs, B loaded inline (warp-level parallelism covers LDS latency)
            #pragma unroll
            for (int nb = 0; nb < 8; nb++) {
                uint32_t b0, b1;
                uint32_t ad = dbB + (uint32_t)((ks * 512 + nb * 64 + lane * 2) * 4);
                asm volatile("ld.shared.v2.b32 {%0,%1}, [%2];"
                             : "=r"(b0), "=r"(b1) : "r"(ad));
                MMA_F16(acc[nb], aF, b0, b1);
            }
        }
        __syncthreads();   // license stage st for overwrite by chunk t+2
    }

    // ---- epilogue: park logits in smem (overlays A stages) ----
    float* ls = (float*)smem;   // [BM][LS_STRIDE] = 69632 B <= SMEM_TOTAL
    #pragma unroll
    for (int nb = 0; nb < 8; nb++) {
        int r = r0w + g;
        int c = nb * 8 + tg * 2;
        *(float2*)&ls[r * LS_STRIDE + c]       = make_float2(acc[nb][0], acc[nb][1]);
        *(float2*)&ls[(r + 8) * LS_STRIDE + c] = make_float2(acc[nb][2], acc[nb][3]);
    }
    __syncthreads();

    float* out_p = out;
    float* out_e = out + (size_t)NTOK * KEXP;
    float* out_l = out_e + NTOK;

    if (tid < BM) {
        const int row = tid;
        const float* lrow = &ls[row * LS_STRIDE];
        float m1 = -1e30f, m2 = -1e30f, m3 = -1e30f;
        int i1 = 0, i2 = 0;
        #pragma unroll
        for (int c = 0; c < KEXP; c++) {
            float v = lrow[c] + s_bias[c];
            if (v > m1)      { m3 = m2; m2 = m1; i2 = i1; m1 = v; i1 = c; }
            else if (v > m2) { m3 = m2; m2 = v;  i2 = c; }
            else if (v > m3) { m3 = v; }
        }
        // near-tie at top-2/top-3 boundary -> exact fp32 repair
        if (m2 - m3 < TIE_TAU) {
            int slot = atomicAdd(&g_cnt, 1);
            if (slot < MAXFIX) g_rows[slot] = row0 + row;
        }
        float Z = 0.f;
        #pragma unroll
        for (int c = 0; c < KEXP; c++) Z += expf(lrow[c] + s_bias[c] - m1);
        float p1 = 1.0f / Z;
        float p2 = expf(m2 - m1) / Z;
        float denom = p1 + p2 + 1e-9f;
        float q1 = p1 / denom, q2 = p2 / denom;
        float ent = -(q1 * logf(fmaxf(q1, 1e-12f)) + q2 * logf(fmaxf(q2, 1e-12f)));
        s_i1[row] = i1; s_i2[row] = i2; s_q1[row] = q1; s_q2[row] = q2;
        out_e[row0 + row] = ent;
    }
    __syncthreads();

    // coalesced sweep: top2_probs + logits (+bias), 256 rows x 16 float4
    #pragma unroll
    for (int i = 0; i < 8; i++) {
        int idx = tid + NTHR * i;       // 0..4095
        int row = idx >> 4;
        int col = (idx & 15) * 4;
        int i1 = s_i1[row], i2 = s_i2[row];
        float q1 = s_q1[row], q2 = s_q2[row];
        float4 pv;
        pv.x = (col + 0 == i1) ? q1 : ((col + 0 == i2) ? q2 : 0.f);
        pv.y = (col + 1 == i1) ? q1 : ((col + 1 == i2) ? q2 : 0.f);
        pv.z = (col + 2 == i1) ? q1 : ((col + 2 == i2) ? q2 : 0.f);
        pv.w = (col + 3 == i1) ? q1 : ((col + 3 == i2) ? q2 : 0.f);
        float4 lv;
        lv.x = ls[row * LS_STRIDE + col + 0] + s_bias[col + 0];
        lv.y = ls[row * LS_STRIDE + col + 1] + s_bias[col + 1];
        lv.z = ls[row * LS_STRIDE + col + 2] + s_bias[col + 2];
        lv.w = ls[row * LS_STRIDE + col + 3] + s_bias[col + 3];
        size_t gaddr = (size_t)(row0 + row) * KEXP + col;
        *(float4*)&out_p[gaddr] = pv;
        *(float4*)&out_l[gaddr] = lv;
    }
}

// exact-fp32 repair for near-tie rows
__global__ void __launch_bounds__(256, 4)
fix_kernel(const float* __restrict__ x, const float* __restrict__ W,
           const float* __restrict__ b, float* __restrict__ out) {
    __shared__ float sx[DDIM];
    __shared__ float sl[KEXP];
    const int tid = threadIdx.x;
    const int e   = tid >> 2;
    const int p   = tid & 3;
    const int n   = min(g_cnt, MAXFIX);

    float* out_p = out;
    float* out_e = out + (size_t)NTOK * KEXP;
    float* out_l = out_e + NTOK;

    for (int i = blockIdx.x; i < n; i += gridDim.x) {
        const int row = g_rows[i];
        for (int j = tid; j < DDIM; j += 256)
            sx[j] = x[(size_t)row * DDIM + j];
        __syncthreads();

        float s = 0.f;
        const float* wr = W + (size_t)e * DDIM + p;
        #pragma unroll 8
        for (int j = 0; j < DDIM / 4; j++)
            s = fmaf(sx[p + 4 * j], wr[4 * j], s);
        s += __shfl_xor_sync(0xFFFFFFFFu, s, 1);
        s += __shfl_xor_sync(0xFFFFFFFFu, s, 2);
        if (p == 0) sl[e] = s + b[e];
        __syncthreads();

        if (tid < KEXP) {
            float m1 = -1e30f, m2 = -1e30f;
            int i1 = 0, i2 = 0;
            #pragma unroll
            for (int c = 0; c < KEXP; c++) {
                float v = sl[c];
                if (v > m1)      { m2 = m1; i2 = i1; m1 = v; i1 = c; }
                else if (v > m2) { m2 = v;  i2 = c; }
            }
            float Z = 0.f;
            #pragma unroll
            for (int c = 0; c < KEXP; c++) Z += expf(sl[c] - m1);
            float p1 = 1.0f / Z;
            float p2 = expf(m2 - m1) / Z;
            float denom = p1 + p2 + 1e-9f;
            float q1 = p1 / denom, q2 = p2 / denom;
            size_t gr = (size_t)row * KEXP;
            out_l[gr + tid] = sl[tid];
            out_p[gr + tid] = (tid == i1) ? q1 : ((tid == i2) ? q2 : 0.f);
            if (tid == 0)
                out_e[row] = -(q1 * logf(fmaxf(q1, 1e-12f)) +
                               q2 * logf(fmaxf(q2, 1e-12f)));
        }
        __syncthreads();
    }
}

extern "C" void kernel_launch(void* const* d_in, const int* in_sizes, int n_in,
                              void* d_out, int out_size) {
    const float* x = (const float*)d_in[0];
    const float* W = (const float*)d_in[1];
    const float* b = (const float*)d_in[2];
    cudaFuncSetAttribute(top2gate_tc, cudaFuncAttributeMaxDynamicSharedMemorySize, SMEM_TOTAL);
    wprep_kernel<<<256, 256>>>(W);
    top2gate_tc<<<NTOK / BM, NTHR, SMEM_TOTAL>>>(x, b, (float*)d_out);
    fix_kernel<<<148, 256>>>(x, W, b, (float*)d_out);
}

// round 15
// speedup vs baseline: 1.2736x; 1.0789x over previous
#include <cuda_runtime.h>
#include <cstdint>

#define NTOK 65536
#define DDIM 2048
#define KEXP 64
#define BM   64                      // rows per tile
#define NTILES (NTOK / BM)           // 1024
#define KC   32
#define NCHUNK (DDIM / KC)           // 64
#define NST  8                       // pipeline stages
#define AROWB 144                    // bytes per A row in stage (128 data + 16 pad)
#define A_BYTES (BM * AROWB)         // 9216
#define B_BYTES 4096
#define STAGE_BYTES (A_BYTES + B_BYTES)   // 13312
#define SM_STAGE0 512
#define SMEM_TOTAL (SM_STAGE0 + NST * STAGE_BYTES)   // 107008
#define GRID 296
#define NTHR 192                     // warps 0-3 consumers, 4-5 producers
#define TIE_TAU 2e-3f
#define MAXFIX 8192

// W pre-converted to fp16, FRAGMENT-MAJOR for m16n8k16 B operand (R8 layout)
__device__ uint32_t g_Wf[128 * 8 * 64];
__device__ int g_cnt;
__device__ int g_rows[MAXFIX];

#define CVT_F16X2(res, f_lo, f_hi) \
    asm("cvt.rn.f16x2.f32 %0, %1, %2;" : "=r"(res) : "f"(f_hi), "f"(f_lo))

__global__ void wprep_kernel(const float* __restrict__ W) {
    int i = blockIdx.x * 256 + threadIdx.x;          // 0 .. 65535
    if (i == 0) g_cnt = 0;
    int reg  = i & 1;
    int lane = (i >> 1) & 31;
    int nb   = (i >> 6) & 7;
    int kb   = i >> 9;
    int n  = nb * 8 + (lane >> 2);
    int k0 = kb * 16 + (lane & 3) * 2 + reg * 8;
    float v0 = W[n * DDIM + k0];
    float v1 = W[n * DDIM + k0 + 1];
    uint32_t w;
    CVT_F16X2(w, v0, v1);
    g_Wf[i] = w;
}

#define CP16(dst_u32, src_ptr) \
    asm volatile("cp.async.cg.shared.global [%0], [%1], 16;" :: "r"(dst_u32), "l"(src_ptr))
#define MBARRIER_INIT(addr, cnt) \
    asm volatile("mbarrier.init.shared.b64 [%0], %1;" :: "r"((uint32_t)(addr)), "r"((uint32_t)(cnt)) : "memory")
#define MBARRIER_ARRIVE(addr) \
    asm volatile("mbarrier.arrive.shared::cta.b64 _, [%0];" :: "r"((uint32_t)(addr)) : "memory")
// .noinc: completion-arrive counts AGAINST the init expected-count (plain form
// self-balances by incrementing pend_count first -> deadlock with init-count protocol)
#define CPASYNC_MBAR_ARRIVE(addr) \
    asm volatile("cp.async.mbarrier.arrive.noinc.shared::cta.b64 [%0];" :: "r"((uint32_t)(addr)) : "memory")
#define MBARRIER_WAIT_PARITY(mbar, par) do { \
    uint32_t _m = (uint32_t)(mbar); uint32_t _p = (uint32_t)(par); uint32_t _d; \
    asm volatile("{\n\t.reg .pred p;\n\t" \
        "mbarrier.try_wait.parity.acquire.cta.shared::cta.b64 p, [%1], %2;\n\t" \
        "selp.b32 %0, 1, 0, p;\n\t}" : "=r"(_d) : "r"(_m), "r"(_p) : "memory"); \
    if (!_d) { \
        asm volatile("{\n\t.reg .pred P1;\n\t" \
            "WL_%=:\n\t" \
            "mbarrier.try_wait.parity.acquire.cta.shared::cta.b64 P1, [%0], %1, 0x989680;\n\t" \
            "@P1 bra.uni WD_%=;\n\t" \
            "bra.uni WL_%=;\n\t" \
            "WD_%=:\n\t}" :: "r"(_m), "r"(_p) : "memory"); \
    } \
} while (0)

#define MMA_F16(c, a, b0_, b1_) \
    asm volatile("mma.sync.aligned.m16n8k16.row.col.f32.f16.f16.f32 " \
                 "{%0,%1,%2,%3}, {%4,%5,%6,%7}, {%8,%9}, {%0,%1,%2,%3};" \
                 : "+f"((c)[0]), "+f"((c)[1]), "+f"((c)[2]), "+f"((c)[3]) \
                 : "r"((a)[0]), "r"((a)[1]), "r"((a)[2]), "r"((a)[3]), \
                   "r"(b0_), "r"(b1_))

__global__ __launch_bounds__(NTHR, 2)
void top2gate_tc(const float* __restrict__ x,
                 const float* __restrict__ b,
                 float* __restrict__ out) {
    extern __shared__ char smem[];
    uint32_t sb;
    asm("{ .reg .u64 t; cvta.to.shared.u64 t, %1; cvt.u32.u64 %0, t; }"
        : "=r"(sb) : "l"((const void*)smem));
    __shared__ float s_bias[KEXP];

    const int tid  = threadIdx.x;
    const int lane = tid & 31;
    const int wid  = tid >> 5;

    // mbarriers: full[s] at sb + s*8, empty[s] at sb + 64 + s*8
    if (tid == 0) {
        #pragma unroll
        for (int s = 0; s < NST; s++) {
            MBARRIER_INIT(sb + s * 8, 64);        // full: 64 producer threads (.noinc arrives)
            MBARRIER_INIT(sb + 64 + s * 8, 128);  // empty: 128 consumer threads
        }
    }
    if (tid < KEXP) s_bias[tid] = b[tid];
    __syncthreads();

    float* out_p = out;
    float* out_e = out + (size_t)NTOK * KEXP;
    float* out_l = out_e + NTOK;

    if (wid >= 4) {
        // ================= PRODUCER (warps 4,5; 64 threads) =================
        const int pt = tid - 128;                 // 0..63
        int pstep = 0;
        for (int tile = blockIdx.x; tile < NTILES; tile += gridDim.x) {
            const float* xt = x + (size_t)tile * BM * DDIM;
            for (int t = 0; t < NCHUNK; t++) {
                const int s = pstep & (NST - 1);
                if (pstep >= NST)
                    MBARRIER_WAIT_PARITY(sb + 64 + s * 8, ((pstep >> 3) & 1) ^ 1);
                const uint32_t da = sb + SM_STAGE0 + (uint32_t)s * STAGE_BYTES;
                #pragma unroll
                for (int q = 0; q < 8; q++) {
                    int idx = pt + 64 * q;        // 0..511
                    int r   = idx >> 3;           // row 0..63
                    int seg = idx & 7;            // 16B segment
                    CP16(da + (uint32_t)(r * AROWB + seg * 16),
                         xt + (size_t)r * DDIM + t * KC + seg * 4);
                }
                const uint32_t db = da + A_BYTES;
                #pragma unroll
                for (int q = 0; q < 4; q++) {
                    int idx = pt + 64 * q;        // 0..255
                    CP16(db + (uint32_t)idx * 16, (const void*)(g_Wf + t * 1024 + idx * 4));
                }
                CPASYNC_MBAR_ARRIVE(sb + s * 8);
                pstep++;
            }
        }
    } else {
        // ================= CONSUMER (warps 0-3; 128 threads) =================
        const int g  = lane >> 2;
        const int tg = lane & 3;
        int cstep = 0;
        for (int tile = blockIdx.x; tile < NTILES; tile += gridDim.x) {
            float acc[8][4];
            #pragma unroll
            for (int nb = 0; nb < 8; nb++)
                #pragma unroll
                for (int c = 0; c < 4; c++) acc[nb][c] = 0.f;

            for (int t = 0; t < NCHUNK; t++) {
                const int s = cstep & (NST - 1);
                MBARRIER_WAIT_PARITY(sb + s * 8, (cstep >> 3) & 1);
                const uint32_t da = sb + SM_STAGE0 + (uint32_t)s * STAGE_BYTES;
                const uint32_t db = da + A_BYTES;
                const float* A = (const float*)(smem + SM_STAGE0 + (size_t)s * STAGE_BYTES);
                #pragma unroll
                for (int ks = 0; ks < 2; ks++) {
                    uint32_t aF[4];
                    {
                        const int r = wid * 16 + g;
                        const int c0 = ks * 16 + tg * 2;
                        const float* Ar = A + r * 36;       // 36 words = 144B row
                        float2 p0 = *(const float2*)(Ar + c0);
                        float2 p1 = *(const float2*)(Ar + 8 * 36 + c0);
                        float2 p2 = *(const float2*)(Ar + c0 + 8);
                        float2 p3 = *(const float2*)(Ar + 8 * 36 + c0 + 8);
                        CVT_F16X2(aF[0], p0.x, p0.y);
                        CVT_F16X2(aF[1], p1.x, p1.y);
                        CVT_F16X2(aF[2], p2.x, p2.y);
                        CVT_F16X2(aF[3], p3.x, p3.y);
                    }
                    #pragma unroll
                    for (int nb = 0; nb < 8; nb++) {
                        uint32_t b0, b1;
                        uint32_t ad = db + (uint32_t)((ks * 512 + nb * 64 + lane * 2) * 4);
                        asm volatile("ld.shared.v2.b32 {%0,%1}, [%2];"
                                     : "=r"(b0), "=r"(b1) : "r"(ad));
                        MMA_F16(acc[nb], aF, b0, b1);
                    }
                }
                MBARRIER_ARRIVE(sb + 64 + s * 8);
                cstep++;
            }

            // ---- warp-local epilogue for rows rA = tile*64 + wid*16 + g, rB = rA+8 ----
            float vA[16], vB[16];
            #pragma unroll
            for (int nb = 0; nb < 8; nb++) {
                #pragma unroll
                for (int pr = 0; pr < 2; pr++) {
                    float bv = s_bias[nb * 8 + tg * 2 + pr];
                    vA[nb * 2 + pr] = acc[nb][pr] + bv;
                    vB[nb * 2 + pr] = acc[nb][2 + pr] + bv;
                }
            }
            const int rA = tile * BM + wid * 16 + g;
            const int rB = rA + 8;

            #pragma unroll
            for (int half = 0; half < 2; half++) {
                float* v = half ? vB : vA;
                const int row = half ? rB : rA;
                // local top-3 over this lane's 16 columns
                float m1 = -1e30f, m2 = -1e30f, m3 = -1e30f;
                int i1 = 0, i2 = 0;
                #pragma unroll
                for (int j = 0; j < 16; j++) {
                    int c = (j >> 1) * 8 + tg * 2 + (j & 1);
                    float val = v[j];
                    if (val > m1)      { m3 = m2; m2 = m1; i2 = i1; m1 = val; i1 = c; }
                    else if (val > m2) { m3 = m2; m2 = val; i2 = c; }
                    else if (val > m3) { m3 = val; }
                }
                // merge across the 4 lanes of the quad (xor 1, then 2)
                #pragma unroll
                for (int d = 1; d <= 2; d <<= 1) {
                    float om1 = __shfl_xor_sync(0xFFFFFFFFu, m1, d);
                    float om2 = __shfl_xor_sync(0xFFFFFFFFu, m2, d);
                    float om3 = __shfl_xor_sync(0xFFFFFFFFu, m3, d);
                    int   oi1 = __shfl_xor_sync(0xFFFFFFFFu, i1, d);
                    int   oi2 = __shfl_xor_sync(0xFFFFFFFFu, i2, d);
                    float nm1, nm2, nm3; int ni1, ni2;
                    if (om1 > m1) {
                        nm1 = om1; ni1 = oi1;
                        if (m1 > om2) { nm2 = m1;  ni2 = i1;  nm3 = fmaxf(om2, m2); }
                        else          { nm2 = om2; ni2 = oi2; nm3 = fmaxf(m1, om3); }
                    } else {
                        nm1 = m1; ni1 = i1;
                        if (om1 > m2) { nm2 = om1; ni2 = oi1; nm3 = fmaxf(m2, om2); }
                        else          { nm2 = m2;  ni2 = i2;  nm3 = fmaxf(om1, m3); }
                    }
                    m1 = nm1; m2 = nm2; m3 = nm3; i1 = ni1; i2 = ni2;
                }
                // softmax partials
                float z = 0.f;
                #pragma unroll
                for (int j = 0; j < 16; j++) z += expf(v[j] - m1);
                z += __shfl_xor_sync(0xFFFFFFFFu, z, 1);
                z += __shfl_xor_sync(0xFFFFFFFFu, z, 2);
                float p1 = 1.0f / z;
                float p2 = expf(m2 - m1) / z;
                float denom = p1 + p2 + 1e-9f;
                float q1 = p1 / denom, q2 = p2 / denom;
                float ent = -(q1 * logf(fmaxf(q1, 1e-12f)) + q2 * logf(fmaxf(q2, 1e-12f)));
                if (tg == 0) {
                    out_e[row] = ent;
                    if (m2 - m3 < TIE_TAU) {
                        int slot = atomicAdd(&g_cnt, 1);
                        if (slot < MAXFIX) g_rows[slot] = row;
                    }
                }
                // writes: 8 float2 per array
                size_t gr = (size_t)row * KEXP;
                #pragma unroll
                for (int nb = 0; nb < 8; nb++) {
                    int c = nb * 8 + tg * 2;
                    float2 lv = make_float2(v[nb * 2], v[nb * 2 + 1]);
                    float2 pv;
                    pv.x = (c == i1)     ? q1 : ((c == i2)     ? q2 : 0.f);
                    pv.y = (c + 1 == i1) ? q1 : ((c + 1 == i2) ? q2 : 0.f);
                    *(float2*)(out_l + gr + c) = lv;
                    *(float2*)(out_p + gr + c) = pv;
                }
            }
        }
    }
}

// exact-fp32 repair for near-tie rows
__global__ void __launch_bounds__(256, 4)
fix_kernel(const float* __restrict__ x, const float* __restrict__ W,
           const float* __restrict__ b, float* __restrict__ out) {
    __shared__ float sx[DDIM];
    __shared__ float sl[KEXP];
    const int tid = threadIdx.x;
    const int e   = tid >> 2;
    const int p   = tid & 3;
    const int n   = min(g_cnt, MAXFIX);

    float* out_p = out;
    float* out_e = out + (size_t)NTOK * KEXP;
    float* out_l = out_e + NTOK;

    for (int i = blockIdx.x; i < n; i += gridDim.x) {
        const int row = g_rows[i];
        for (int j = tid; j < DDIM; j += 256)
            sx[j] = x[(size_t)row * DDIM + j];
        __syncthreads();

        float s = 0.f;
        const float* wr = W + (size_t)e * DDIM + p;
        #pragma unroll 8
        for (int j = 0; j < DDIM / 4; j++)
            s = fmaf(sx[p + 4 * j], wr[4 * j], s);
        s += __shfl_xor_sync(0xFFFFFFFFu, s, 1);
        s += __shfl_xor_sync(0xFFFFFFFFu, s, 2);
        if (p == 0) sl[e] = s + b[e];
        __syncthreads();

        if (tid < KEXP) {
            float m1 = -1e30f, m2 = -1e30f;
            int i1 = 0, i2 = 0;
            #pragma unroll
            for (int c = 0; c < KEXP; c++) {
                float v = sl[c];
                if (v > m1)      { m2 = m1; i2 = i1; m1 = v; i1 = c; }
                else if (v > m2) { m2 = v;  i2 = c; }
            }
            float Z = 0.f;
            #pragma unroll
            for (int c = 0; c < KEXP; c++) Z += expf(sl[c] - m1);
            float p1 = 1.0f / Z;
            float p2 = expf(m2 - m1) / Z;
            float denom = p1 + p2 + 1e-9f;
            float q1 = p1 / denom, q2 = p2 / denom;
            size_t gr = (size_t)row * KEXP;
            out_l[gr + tid] = sl[tid];
            out_p[gr + tid] = (tid == i1) ? q1 : ((tid == i2) ? q2 : 0.f);
            if (tid == 0)
                out_e[row] = -(q1 * logf(fmaxf(q1, 1e-12f)) +
                               q2 * logf(fmaxf(q2, 1e-12f)));
        }
        __syncthreads();
    }
}

extern "C" void kernel_launch(void* const* d_in, const int* in_sizes, int n_in,
                              void* d_out, int out_size) {
    const float* x = (const float*)d_in[0];
    const float* W = (const float*)d_in[1];
    const float* b = (const float*)d_in[2];
    cudaFuncSetAttribute(top2gate_tc, cudaFuncAttributeMaxDynamicSharedMemorySize, SMEM_TOTAL);
    wprep_kernel<<<256, 256>>>(W);
    top2gate_tc<<<GRID, NTHR, SMEM_TOTAL>>>(x, b, (float*)d_out);
    fix_kernel<<<148, 256>>>(x, W, b, (float*)d_out);
}

// round 16
// speedup vs baseline: 1.2870x; 1.0105x over previous
#include <cuda_runtime.h>
#include <cstdint>

#define NTOK 65536
#define DDIM 2048
#define KEXP 64
#define BM   64                      // rows per tile
#define NTILES (NTOK / BM)           // 1024
#define KC   32
#define NCHUNK (DDIM / KC)           // 64
#define NST  8                       // pipeline stages
#define AROWB 144                    // bytes per A row in stage (128 data + 16 pad)
#define A_BYTES (BM * AROWB)         // 9216
#define B_BYTES 4096
#define STAGE_BYTES (A_BYTES + B_BYTES)   // 13312
#define SM_STAGE0 512
#define SMEM_TOTAL (SM_STAGE0 + NST * STAGE_BYTES)   // 107008
#define GRID 296
#define NTHR 192                     // warps 0-3 consumers, 4-5 producers
#define TF_OFF 128                   // tile-ring full barriers (4 x 8B)
#define TE_OFF 160                   // tile-ring empty barriers
#define ST_TILE 192                  // tile-id ring (4 x 4B)
#define NTQ 4
#define TIE_TAU 2e-3f
#define MAXFIX 8192

// W pre-converted to fp16, FRAGMENT-MAJOR for m16n8k16 B operand (R8 layout)
__device__ uint32_t g_Wf[128 * 8 * 64];
__device__ int g_cnt;
__device__ int g_rows[MAXFIX];
__device__ unsigned g_tile;

#define CVT_F16X2(res, f_lo, f_hi) \
    asm("cvt.rn.f16x2.f32 %0, %1, %2;" : "=r"(res) : "f"(f_hi), "f"(f_lo))

__global__ void wprep_kernel(const float* __restrict__ W) {
    int i = blockIdx.x * 256 + threadIdx.x;          // 0 .. 65535
    if (i == 0) { g_cnt = 0; g_tile = 0u; }          // reset per launch (graph-safe)
    int reg  = i & 1;
    int lane = (i >> 1) & 31;
    int nb   = (i >> 6) & 7;
    int kb   = i >> 9;
    int n  = nb * 8 + (lane >> 2);
    int k0 = kb * 16 + (lane & 3) * 2 + reg * 8;
    float v0 = W[n * DDIM + k0];
    float v1 = W[n * DDIM + k0 + 1];
    uint32_t w;
    CVT_F16X2(w, v0, v1);
    g_Wf[i] = w;
}

#define CP16(dst_u32, src_ptr) \
    asm volatile("cp.async.cg.shared.global [%0], [%1], 16;" :: "r"(dst_u32), "l"(src_ptr))
#define MBARRIER_INIT(addr, cnt) \
    asm volatile("mbarrier.init.shared.b64 [%0], %1;" :: "r"((uint32_t)(addr)), "r"((uint32_t)(cnt)) : "memory")
#define MBARRIER_ARRIVE(addr) \
    asm volatile("mbarrier.arrive.shared::cta.b64 _, [%0];" :: "r"((uint32_t)(addr)) : "memory")
#define CPASYNC_MBAR_ARRIVE(addr) \
    asm volatile("cp.async.mbarrier.arrive.noinc.shared::cta.b64 [%0];" :: "r"((uint32_t)(addr)) : "memory")
#define MBARRIER_WAIT_PARITY(mbar, par) do { \
    uint32_t _m = (uint32_t)(mbar); uint32_t _p = (uint32_t)(par); uint32_t _d; \
    asm volatile("{\n\t.reg .pred p;\n\t" \
        "mbarrier.try_wait.parity.acquire.cta.shared::cta.b64 p, [%1], %2;\n\t" \
        "selp.b32 %0, 1, 0, p;\n\t}" : "=r"(_d) : "r"(_m), "r"(_p) : "memory"); \
    if (!_d) { \
        asm volatile("{\n\t.reg .pred P1;\n\t" \
            "WL_%=:\n\t" \
            "mbarrier.try_wait.parity.acquire.cta.shared::cta.b64 P1, [%0], %1, 0x989680;\n\t" \
            "@P1 bra.uni WD_%=;\n\t" \
            "bra.uni WL_%=;\n\t" \
            "WD_%=:\n\t}" :: "r"(_m), "r"(_p) : "memory"); \
    } \
} while (0)

#define MMA_F16(c, a, b0_, b1_) \
    asm volatile("mma.sync.aligned.m16n8k16.row.col.f32.f16.f16.f32 " \
                 "{%0,%1,%2,%3}, {%4,%5,%6,%7}, {%8,%9}, {%0,%1,%2,%3};" \
                 : "+f"((c)[0]), "+f"((c)[1]), "+f"((c)[2]), "+f"((c)[3]) \
                 : "r"((a)[0]), "r"((a)[1]), "r"((a)[2]), "r"((a)[3]), \
                   "r"(b0_), "r"(b1_))

__global__ __launch_bounds__(NTHR, 2)
void top2gate_tc(const float* __restrict__ x,
                 const float* __restrict__ b,
                 float* __restrict__ out) {
    extern __shared__ char smem[];
    uint32_t sb;
    asm("{ .reg .u64 t; cvta.to.shared.u64 t, %1; cvt.u32.u64 %0, t; }"
        : "=r"(sb) : "l"((const void*)smem));
    __shared__ float s_bias[KEXP];

    const int tid  = threadIdx.x;
    const int lane = tid & 31;
    const int wid  = tid >> 5;

    // stage barriers: full[s] at sb+s*8, empty[s] at sb+64+s*8
    // tile ring:      tf[q] at sb+TF_OFF+q*8 (count 1), te[q] at sb+TE_OFF+q*8 (count 128)
    if (tid == 0) {
        #pragma unroll
        for (int s = 0; s < NST; s++) {
            MBARRIER_INIT(sb + s * 8, 64);        // full: 64 producer threads (.noinc)
            MBARRIER_INIT(sb + 64 + s * 8, 128);  // empty: 128 consumer threads
        }
        #pragma unroll
        for (int q = 0; q < NTQ; q++) {
            MBARRIER_INIT(sb + TF_OFF + q * 8, 1);
            MBARRIER_INIT(sb + TE_OFF + q * 8, 128);
        }
    }
    if (tid < KEXP) s_bias[tid] = b[tid];
    __syncthreads();

    float* out_p = out;
    float* out_e = out + (size_t)NTOK * KEXP;
    float* out_l = out_e + NTOK;

    volatile int* tring = (volatile int*)(smem + ST_TILE);

    if (wid >= 4) {
        // ================= PRODUCER (warps 4,5; 64 threads) =================
        const int pt = tid - 128;                 // 0..63
        int pstep = 0;
        for (int k = 0; ; k++) {
            const int q = k & (NTQ - 1);
            if (pt == 0) {
                if (k >= NTQ)
                    MBARRIER_WAIT_PARITY(sb + TE_OFF + q * 8, ((k >> 2) & 1) ^ 1);
                unsigned t = atomicAdd(&g_tile, 1u);
                tring[q] = (int)t;
                MBARRIER_ARRIVE(sb + TF_OFF + q * 8);   // release: publishes tring[q]
            }
            MBARRIER_WAIT_PARITY(sb + TF_OFF + q * 8, (k >> 2) & 1);
            const int tile = tring[q];
            if (tile >= NTILES) break;

            const float* xt = x + (size_t)tile * BM * DDIM;
            for (int t = 0; t < NCHUNK; t++) {
                const int s = pstep & (NST - 1);
                if (pstep >= NST)
                    MBARRIER_WAIT_PARITY(sb + 64 + s * 8, ((pstep >> 3) & 1) ^ 1);
                const uint32_t da = sb + SM_STAGE0 + (uint32_t)s * STAGE_BYTES;
                #pragma unroll
                for (int qq = 0; qq < 8; qq++) {
                    int idx = pt + 64 * qq;       // 0..511
                    int r   = idx >> 3;           // row 0..63
                    int seg = idx & 7;            // 16B segment
                    CP16(da + (uint32_t)(r * AROWB + seg * 16),
                         xt + (size_t)r * DDIM + t * KC + seg * 4);
                }
                const uint32_t db = da + A_BYTES;
                #pragma unroll
                for (int qq = 0; qq < 4; qq++) {
                    int idx = pt + 64 * qq;       // 0..255
                    CP16(db + (uint32_t)idx * 16, (const void*)(g_Wf + t * 1024 + idx * 4));
                }
                CPASYNC_MBAR_ARRIVE(sb + s * 8);
                pstep++;
            }
        }
    } else {
        // ================= CONSUMER (warps 0-3; 128 threads) =================
        const int g  = lane >> 2;
        const int tg = lane & 3;
        int cstep = 0;
        for (int k = 0; ; k++) {
            const int q = k & (NTQ - 1);
            MBARRIER_WAIT_PARITY(sb + TF_OFF + q * 8, (k >> 2) & 1);
            const int tile = tring[q];
            if (tile >= NTILES) break;

            float acc[8][4];
            #pragma unroll
            for (int nb = 0; nb < 8; nb++)
                #pragma unroll
                for (int c = 0; c < 4; c++) acc[nb][c] = 0.f;

            for (int t = 0; t < NCHUNK; t++) {
                const int s = cstep & (NST - 1);
                MBARRIER_WAIT_PARITY(sb + s * 8, (cstep >> 3) & 1);
                const uint32_t da = sb + SM_STAGE0 + (uint32_t)s * STAGE_BYTES;
                const uint32_t db = da + A_BYTES;
                const float* A = (const float*)(smem + SM_STAGE0 + (size_t)s * STAGE_BYTES);
                #pragma unroll
                for (int ks = 0; ks < 2; ks++) {
                    uint32_t aF[4];
                    {
                        const int r = wid * 16 + g;
                        const int c0 = ks * 16 + tg * 2;
                        const float* Ar = A + r * 36;       // 36 words = 144B row
                        float2 p0 = *(const float2*)(Ar + c0);
                        float2 p1 = *(const float2*)(Ar + 8 * 36 + c0);
                        float2 p2 = *(const float2*)(Ar + c0 + 8);
                        float2 p3 = *(const float2*)(Ar + 8 * 36 + c0 + 8);
                        CVT_F16X2(aF[0], p0.x, p0.y);
                        CVT_F16X2(aF[1], p1.x, p1.y);
                        CVT_F16X2(aF[2], p2.x, p2.y);
                        CVT_F16X2(aF[3], p3.x, p3.y);
                    }
                    #pragma unroll
                    for (int nb = 0; nb < 8; nb++) {
                        uint32_t b0, b1;
                        uint32_t ad = db + (uint32_t)((ks * 512 + nb * 64 + lane * 2) * 4);
                        asm volatile("ld.shared.v2.b32 {%0,%1}, [%2];"
                                     : "=r"(b0), "=r"(b1) : "r"(ad));
                        MMA_F16(acc[nb], aF, b0, b1);
                    }
                }
                MBARRIER_ARRIVE(sb + 64 + s * 8);
                cstep++;
            }

            // ---- warp-local epilogue for rows rA = tile*64 + wid*16 + g, rB = rA+8 ----
            float vA[16], vB[16];
            #pragma unroll
            for (int nb = 0; nb < 8; nb++) {
                #pragma unroll
                for (int pr = 0; pr < 2; pr++) {
                    float bv = s_bias[nb * 8 + tg * 2 + pr];
                    vA[nb * 2 + pr] = acc[nb][pr] + bv;
                    vB[nb * 2 + pr] = acc[nb][2 + pr] + bv;
                }
            }
            const int rA = tile * BM + wid * 16 + g;
            const int rB = rA + 8;

            #pragma unroll
            for (int half = 0; half < 2; half++) {
                float* v = half ? vB : vA;
                const int row = half ? rB : rA;
                float m1 = -1e30f, m2 = -1e30f, m3 = -1e30f;
                int i1 = 0, i2 = 0;
                #pragma unroll
                for (int j = 0; j < 16; j++) {
                    int c = (j >> 1) * 8 + tg * 2 + (j & 1);
                    float val = v[j];
                    if (val > m1)      { m3 = m2; m2 = m1; i2 = i1; m1 = val; i1 = c; }
                    else if (val > m2) { m3 = m2; m2 = val; i2 = c; }
                    else if (val > m3) { m3 = val; }
                }
                #pragma unroll
                for (int d = 1; d <= 2; d <<= 1) {
                    float om1 = __shfl_xor_sync(0xFFFFFFFFu, m1, d);
                    float om2 = __shfl_xor_sync(0xFFFFFFFFu, m2, d);
                    float om3 = __shfl_xor_sync(0xFFFFFFFFu, m3, d);
                    int   oi1 = __shfl_xor_sync(0xFFFFFFFFu, i1, d);
                    int   oi2 = __shfl_xor_sync(0xFFFFFFFFu, i2, d);
                    float nm1, nm2, nm3; int ni1, ni2;
                    if (om1 > m1) {
                        nm1 = om1; ni1 = oi1;
                        if (m1 > om2) { nm2 = m1;  ni2 = i1;  nm3 = fmaxf(om2, m2); }
                        else          { nm2 = om2; ni2 = oi2; nm3 = fmaxf(m1, om3); }
                    } else {
                        nm1 = m1; ni1 = i1;
                        if (om1 > m2) { nm2 = om1; ni2 = oi1; nm3 = fmaxf(m2, om2); }
                        else          { nm2 = m2;  ni2 = i2;  nm3 = fmaxf(om1, m3); }
                    }
                    m1 = nm1; m2 = nm2; m3 = nm3; i1 = ni1; i2 = ni2;
                }
                float z = 0.f;
                #pragma unroll
                for (int j = 0; j < 16; j++) z += expf(v[j] - m1);
                z += __shfl_xor_sync(0xFFFFFFFFu, z, 1);
                z += __shfl_xor_sync(0xFFFFFFFFu, z, 2);
                float p1 = 1.0f / z;
                float p2 = expf(m2 - m1) / z;
                float denom = p1 + p2 + 1e-9f;
                float q1 = p1 / denom, q2 = p2 / denom;
                float ent = -(q1 * logf(fmaxf(q1, 1e-12f)) + q2 * logf(fmaxf(q2, 1e-12f)));
                if (tg == 0) {
                    out_e[row] = ent;
                    if (m2 - m3 < TIE_TAU) {
                        int slot = atomicAdd(&g_cnt, 1);
                        if (slot < MAXFIX) g_rows[slot] = row;
                    }
                }
                size_t gr = (size_t)row * KEXP;
                #pragma unroll
                for (int nb = 0; nb < 8; nb++) {
                    int c = nb * 8 + tg * 2;
                    float2 lv = make_float2(v[nb * 2], v[nb * 2 + 1]);
                    float2 pv;
                    pv.x = (c == i1)     ? q1 : ((c == i2)     ? q2 : 0.f);
                    pv.y = (c + 1 == i1) ? q1 : ((c + 1 == i2) ? q2 : 0.f);
                    *(float2*)(out_l + gr + c) = lv;
                    *(float2*)(out_p + gr + c) = pv;
                }
            }
            MBARRIER_ARRIVE(sb + TE_OFF + q * 8);   // release tile-ring slot q
        }
    }
}

// exact-fp32 repair for near-tie rows
__global__ void __launch_bounds__(256, 4)
fix_kernel(const float* __restrict__ x, const float* __restrict__ W,
           const float* __restrict__ b, float* __restrict__ out) {
    __shared__ float sx[DDIM];
    __shared__ float sl[KEXP];
    const int tid = threadIdx.x;
    const int e   = tid >> 2;
    const int p   = tid & 3;
    const int n   = min(g_cnt, MAXFIX);

    float* out_p = out;
    float* out_e = out + (size_t)NTOK * KEXP;
    float* out_l = out_e + NTOK;

    for (int i = blockIdx.x; i < n; i += gridDim.x) {
        const int row = g_rows[i];
        for (int j = tid; j < DDIM; j += 256)
            sx[j] = x[(size_t)row * DDIM + j];
        __syncthreads();

        float s = 0.f;
        const float* wr = W + (size_t)e * DDIM + p;
        #pragma unroll 8
        for (int j = 0; j < DDIM / 4; j++)
            s = fmaf(sx[p + 4 * j], wr[4 * j], s);
        s += __shfl_xor_sync(0xFFFFFFFFu, s, 1);
        s += __shfl_xor_sync(0xFFFFFFFFu, s, 2);
        if (p == 0) sl[e] = s + b[e];
        __syncthreads();

        if (tid < KEXP) {
            float m1 = -1e30f, m2 = -1e30f;
            int i1 = 0, i2 = 0;
            #pragma unroll
            for (int c = 0; c < KEXP; c++) {
                float v = sl[c];
                if (v > m1)      { m2 = m1; i2 = i1; m1 = v; i1 = c; }
                else if (v > m2) { m2 = v;  i2 = c; }
            }
            float Z = 0.f;
            #pragma unroll
            for (int c = 0; c < KEXP; c++) Z += expf(sl[c] - m1);
            float p1 = 1.0f / Z;
            float p2 = expf(m2 - m1) / Z;
            float denom = p1 + p2 + 1e-9f;
            float q1 = p1 / denom, q2 = p2 / denom;
            size_t gr = (size_t)row * KEXP;
            out_l[gr + tid] = sl[tid];
            out_p[gr + tid] = (tid == i1) ? q1 : ((tid == i2) ? q2 : 0.f);
            if (tid == 0)
                out_e[row] = -(q1 * logf(fmaxf(q1, 1e-12f)) +
                               q2 * logf(fmaxf(q2, 1e-12f)));
        }
        __syncthreads();
    }
}

extern "C" void kernel_launch(void* const* d_in, const int* in_sizes, int n_in,
                              void* d_out, int out_size) {
    const float* x = (const float*)d_in[0];
    const float* W = (const float*)d_in[1];
    const float* b = (const float*)d_in[2];
    cudaFuncSetAttribute(top2gate_tc, cudaFuncAttributeMaxDynamicSharedMemorySize, SMEM_TOTAL);
    wprep_kernel<<<256, 256>>>(W);
    top2gate_tc<<<GRID, NTHR, SMEM_TOTAL>>>(x, b, (float*)d_out);
    fix_kernel<<<148, 256>>>(x, W, b, (float*)d_out);
}